// round 7
// baseline (speedup 1.0000x reference)
#include <cuda_runtime.h>
#include <cstdint>

// Causal muP attention (scale=1/dhead), B=2 H=16 L=2048 D=64, fp32 in/out.
// FA2 + mma.sync.m16n8k8 TF32, 4 warps x 32 q-rows, double-buffered K/V.
// R7: odd-fastest fragment word layout -> K/V scatter is 16 STS.64 per thread
//     (was 32 STS.32), wavefronts halve. RNA tf32 restored on K/V.
//     No online softmax (muP scale => fixed max 0), O never rescaled.

#define BM 128
#define BN 64
#define DD 64
#define NTHREADS 128

#define QF_FLOATS 8192           // [rowblk 0..7][kt][lane][4]
#define KF_FLOATS 4096           // per buffer: [kt][p][ln^kt][reg*2+odd]
#define VF_FLOATS 4096           // per buffer: [kt][pd][ln^pd][regv*2+odd]
#define SMEM_FLOATS (QF_FLOATS + 2*KF_FLOATS + 2*VF_FLOATS)
#define SMEM_BYTES (SMEM_FLOATS * 4)

__device__ __forceinline__ uint32_t f2tf(float f) {
    uint32_t r;
    asm("cvt.rna.tf32.f32 %0, %1;" : "=r"(r) : "f"(f));
    return r;
}
__device__ __forceinline__ float ex2(float x) {
    float y;
    asm("ex2.approx.f32 %0, %1;" : "=f"(y) : "f"(x));
    return y;
}
__device__ __forceinline__ void mma_tf32(float* d,
                                         uint32_t a0, uint32_t a1, uint32_t a2, uint32_t a3,
                                         uint32_t b0, uint32_t b1) {
    asm volatile(
        "mma.sync.aligned.m16n8k8.row.col.f32.tf32.tf32.f32 "
        "{%0,%1,%2,%3}, {%4,%5,%6,%7}, {%8,%9}, {%0,%1,%2,%3};"
        : "+f"(d[0]), "+f"(d[1]), "+f"(d[2]), "+f"(d[3])
        : "r"(a0), "r"(a1), "r"(a2), "r"(a3), "r"(b0), "r"(b1));
}

// K tile scatter: pairs (n, n+8) -> contiguous float2 (odd-fastest layout).
// kr[t] = K[(tid>>4) + t*8][d4..d4+3];  t even/odd = odd 0/1, p = t>>1.
__device__ __forceinline__ void scatter_k(float* Kc, const float4* kr, int tid) {
    const int d4   = (tid & 15) * 4;
    const int kt   = d4 >> 3;
    const int reg  = (d4 >> 2) & 1;
    const int r    = tid >> 4;                       // 0..7
    const int slot = (r < 4) ? (2 * r) : (2 * r - 7);
    #pragma unroll
    for (int i = 0; i < 4; i++) {                    // p = i
        const float a[4] = {kr[2*i].x,   kr[2*i].y,   kr[2*i].z,   kr[2*i].w};
        const float b[4] = {kr[2*i+1].x, kr[2*i+1].y, kr[2*i+1].z, kr[2*i+1].w};
        #pragma unroll
        for (int e = 0; e < 4; e++) {
            int ln  = (slot * 4 + e) ^ kt;           // swizzle
            int idx = ((kt * 4 + i) * 32 + ln) * 4 + reg * 2;
            *(float2*)(Kc + idx) = make_float2(
                __uint_as_float(f2tf(a[e])), __uint_as_float(f2tf(b[e])));
        }
    }
}
// V tile scatter: pairs (d, d+8) -> contiguous float2 (odd-fastest layout).
// vr[t] = V[kv][d4 + t*8 ..];  t even/odd = odd 0/1, pd = t>>1.
__device__ __forceinline__ void scatter_v(float* Vc, const float4* vr, int tid) {
    const int kv   = tid & 63;
    const int ktv  = kv >> 3;
    const int regv = (kv >> 2) & 1;
    const int ll   = kv & 3;
    const int b7   = (tid >> 6) * 4;                 // (d4 & 7)
    #pragma unroll
    for (int i = 0; i < 4; i++) {                    // pd = i
        const float a[4] = {vr[2*i].x,   vr[2*i].y,   vr[2*i].z,   vr[2*i].w};
        const float b[4] = {vr[2*i+1].x, vr[2*i+1].y, vr[2*i+1].z, vr[2*i+1].w};
        #pragma unroll
        for (int e = 0; e < 4; e++) {
            int ln  = ((b7 + e) * 4 + ll) ^ i;       // swizzle
            int idx = ((ktv * 4 + i) * 32 + ln) * 4 + regv * 2;
            *(float2*)(Vc + idx) = make_float2(
                __uint_as_float(f2tf(a[e])), __uint_as_float(f2tf(b[e])));
        }
    }
}

__global__ __launch_bounds__(NTHREADS, 2)
void fa_tc_kernel(const float* __restrict__ Q, const float* __restrict__ K,
                  const float* __restrict__ V, float* __restrict__ O, int L)
{
    extern __shared__ float sm[];
    float* Qf  = sm;
    float* Kf0 = Qf  + QF_FLOATS;
    float* Kf1 = Kf0 + KF_FLOATS;
    float* Vf0 = Kf1 + KF_FLOATS;
    float* Vf1 = Vf0 + VF_FLOATS;
    float* Kbuf[2] = {Kf0, Kf1};
    float* Vbuf[2] = {Vf0, Vf1};

    const int qi    = (gridDim.x - 1) - blockIdx.x;   // heavy tiles first
    const int bh    = blockIdx.y;
    const int qbase = qi * BM;
    const float qscale = 1.4426950408889634f / 64.0f; // log2(e)/dhead

    const int tid  = threadIdx.x;
    const int w    = tid >> 5;      // warp 0..3, owns rows [w*32, w*32+32)
    const int lane = tid & 31;

    const float* Qg = Q + (size_t)bh * L * DD;
    const float* Kg = K + (size_t)bh * L * DD;
    const float* Vg = V + (size_t)bh * L * DD;
    float*       Og = O + (size_t)bh * L * DD;

    // ---- Q tile -> A-fragment layout (scale + RNA tf32 baked in) ----
    #pragma unroll
    for (int t = 0; t < 16; t++) {
        int fidx = tid + t * NTHREADS;      // 0..2047
        int row  = fidx >> 4;
        int d4   = (fidx & 15) * 4;
        float4 q4 = *(const float4*)(Qg + (size_t)(qbase + row) * DD + d4);
        float qv[4] = {q4.x, q4.y, q4.z, q4.w};
        int ww = row >> 4, rl = row & 15;
        #pragma unroll
        for (int e = 0; e < 4; e++) {
            int d   = d4 + e;
            int kt  = d >> 3;
            int ln  = (rl & 7) * 4 + (d & 3);
            int reg = ((rl >> 3) & 1) + (((d & 7) >= 4) ? 2 : 0);
            Qf[((ww * 8 + kt) * 32 + ln) * 4 + reg] =
                __uint_as_float(f2tf(qv[e] * qscale));
        }
    }

    // ---- prologue: tile 0 into buffer 0 ----
    {
        float4 kr[8], vr[8];
        #pragma unroll
        for (int t = 0; t < 8; t++) {
            int n = (tid >> 4) + t * 8;
            kr[t] = *(const float4*)(Kg + (size_t)n * DD + (tid & 15) * 4);
        }
        #pragma unroll
        for (int t = 0; t < 8; t++) {
            int fi = tid + t * NTHREADS;
            vr[t] = *(const float4*)(Vg + (size_t)(fi & 63) * DD + (fi >> 6) * 4);
        }
        scatter_k(Kf0, kr, tid);
        scatter_v(Vf0, vr, tid);
    }
    __syncthreads();

    // two 16-row halves per warp: h=0 rows w*32+0..15, h=1 rows w*32+16..31
    float s[2][8][4], o[2][8][4];
    float l_[2][2];
    #pragma unroll
    for (int h = 0; h < 2; h++) {
        l_[h][0] = 0.0f; l_[h][1] = 0.0f;
        #pragma unroll
        for (int dt = 0; dt < 8; dt++)
            #pragma unroll
            for (int j = 0; j < 4; j++) o[h][dt][j] = 0.0f;
    }

    const int wrow0 = qbase + w * 32;
    const int njt   = 2 * qi + 2;

    for (int jt = 0; jt < njt; jt++) {
        const int   cur       = jt & 1;
        const bool  have_next = (jt + 1 < njt);
        const int   kbase     = jt * BN;
        const bool  active    = (kbase <= wrow0 + 31);
        const float* Kc = Kbuf[cur];
        const float* Vc = Vbuf[cur];

        // prefetch next K tile to regs (gmem latency hidden by GEMM1)
        float4 kr[8];
        if (have_next) {
            const float* Kn = Kg + (size_t)(kbase + BN) * DD;
            #pragma unroll
            for (int t = 0; t < 8; t++)
                kr[t] = *(const float4*)(Kn + ((tid >> 4) + t * 8) * DD + (tid & 15) * 4);
        }

        // ---- GEMM1: S = Q K^T (B loads shared by both row halves) ----
        if (active) {
            #pragma unroll
            for (int h = 0; h < 2; h++)
                #pragma unroll
                for (int nt = 0; nt < 8; nt++)
                    #pragma unroll
                    for (int j = 0; j < 4; j++) s[h][nt][j] = 0.0f;
            #pragma unroll
            for (int kt = 0; kt < 8; kt++) {
                uint4 A0 = *(const uint4*)&Qf[(((2 * w)     * 8 + kt) * 32 + lane) * 4];
                uint4 A1 = *(const uint4*)&Qf[(((2 * w + 1) * 8 + kt) * 32 + lane) * 4];
                #pragma unroll
                for (int p = 0; p < 4; p++) {
                    // odd-fastest word: (b.x,b.z) = nt even, (b.y,b.w) = nt odd
                    uint4 b = *(const uint4*)&Kc[((kt * 4 + p) * 32 + (lane ^ kt)) * 4];
                    mma_tf32(s[0][2 * p],     A0.x, A0.y, A0.z, A0.w, b.x, b.z);
                    mma_tf32(s[0][2 * p + 1], A0.x, A0.y, A0.z, A0.w, b.y, b.w);
                    mma_tf32(s[1][2 * p],     A1.x, A1.y, A1.z, A1.w, b.x, b.z);
                    mma_tf32(s[1][2 * p + 1], A1.x, A1.y, A1.z, A1.w, b.y, b.w);
                }
            }
        }

        // store next K tile; prefetch next V tile
        float4 vr[8];
        if (have_next) {
            scatter_k(Kbuf[cur ^ 1], kr, tid);
            const float* Vn = Vg + (size_t)(kbase + BN) * DD;
            #pragma unroll
            for (int t = 0; t < 8; t++) {
                int fi = tid + t * NTHREADS;
                vr[t] = *(const float4*)(Vn + (size_t)(fi & 63) * DD + (fi >> 6) * 4);
            }
        }

        if (active) {
            // ---- causal mask (perm-aware: c0<->kv c, c1<->kv c+4) ----
            if (kbase + BN - 1 > wrow0) {
                #pragma unroll
                for (int h = 0; h < 2; h++) {
                    int rA = wrow0 + h * 16 + (lane >> 2);
                    int rB = rA + 8;
                    #pragma unroll
                    for (int nt = 0; nt < 8; nt++) {
                        int col = kbase + nt * 8 + (lane & 3);
                        if (col     > rA) s[h][nt][0] = -1e30f;
                        if (col + 4 > rA) s[h][nt][1] = -1e30f;
                        if (col     > rB) s[h][nt][2] = -1e30f;
                        if (col + 4 > rB) s[h][nt][3] = -1e30f;
                    }
                }
            }
            // ---- softmax numerator, fixed max=0 (muP: |s| << 1) ----
            #pragma unroll
            for (int h = 0; h < 2; h++) {
                float sumA = 0.0f, sumB = 0.0f;
                #pragma unroll
                for (int nt = 0; nt < 8; nt++) {
                    float p0 = ex2(s[h][nt][0]);
                    float p1 = ex2(s[h][nt][1]);
                    float p2 = ex2(s[h][nt][2]);
                    float p3 = ex2(s[h][nt][3]);
                    sumA += p0 + p1;
                    sumB += p2 + p3;
                    s[h][nt][0] = p0;
                    s[h][nt][1] = p1;
                    s[h][nt][2] = p2;
                    s[h][nt][3] = p3;
                }
                l_[h][0] += sumA;
                l_[h][1] += sumB;
            }
            // ---- GEMM2: O += P V (P = s regs, order {0,2,1,3}; shared B) ----
            #pragma unroll
            for (int kt = 0; kt < 8; kt++) {
                uint32_t p00 = __float_as_uint(s[0][kt][0]);
                uint32_t p01 = __float_as_uint(s[0][kt][2]);
                uint32_t p02 = __float_as_uint(s[0][kt][1]);
                uint32_t p03 = __float_as_uint(s[0][kt][3]);
                uint32_t p10 = __float_as_uint(s[1][kt][0]);
                uint32_t p11 = __float_as_uint(s[1][kt][2]);
                uint32_t p12 = __float_as_uint(s[1][kt][1]);
                uint32_t p13 = __float_as_uint(s[1][kt][3]);
                #pragma unroll
                for (int pd = 0; pd < 4; pd++) {
                    // odd-fastest word: (b.x,b.z) = dt even, (b.y,b.w) = dt odd
                    uint4 b = *(const uint4*)&Vc[((kt * 4 + pd) * 32 + (lane ^ pd)) * 4];
                    mma_tf32(o[0][2 * pd],     p00, p01, p02, p03, b.x, b.z);
                    mma_tf32(o[0][2 * pd + 1], p00, p01, p02, p03, b.y, b.w);
                    mma_tf32(o[1][2 * pd],     p10, p11, p12, p13, b.x, b.z);
                    mma_tf32(o[1][2 * pd + 1], p10, p11, p12, p13, b.y, b.w);
                }
            }
        }

        if (have_next) {
            scatter_v(Vbuf[cur ^ 1], vr, tid);
            __syncthreads();
        }
    }

    // ---- epilogue: reduce l across quad, normalize, store ----
    #pragma unroll
    for (int h = 0; h < 2; h++) {
        float lA = l_[h][0], lB = l_[h][1];
        lA += __shfl_xor_sync(0xffffffffu, lA, 1);
        lA += __shfl_xor_sync(0xffffffffu, lA, 2);
        lB += __shfl_xor_sync(0xffffffffu, lB, 1);
        lB += __shfl_xor_sync(0xffffffffu, lB, 2);
        float invA = 1.0f / lA;
        float invB = 1.0f / lB;

        int rA = qbase + w * 32 + h * 16 + (lane >> 2);
        int rB = rA + 8;
        #pragma unroll
        for (int dt = 0; dt < 8; dt++) {
            int d0 = dt * 8 + 2 * (lane & 3);
            float2 oa = make_float2(o[h][dt][0] * invA, o[h][dt][1] * invA);
            float2 ob = make_float2(o[h][dt][2] * invB, o[h][dt][3] * invB);
            *(float2*)(Og + (size_t)rA * DD + d0) = oa;
            *(float2*)(Og + (size_t)rB * DD + d0) = ob;
        }
    }
}

extern "C" void kernel_launch(void* const* d_in, const int* in_sizes, int n_in,
                              void* d_out, int out_size)
{
    const float* Q = (const float*)d_in[0];
    const float* K = (const float*)d_in[1];
    const float* V = (const float*)d_in[2];
    float* O = (float*)d_out;

    const int L  = 2048;
    const int BH = 2 * 16;

    cudaFuncSetAttribute(fa_tc_kernel,
                         cudaFuncAttributeMaxDynamicSharedMemorySize, SMEM_BYTES);

    dim3 grid(L / BM, BH);    // (16, 32)
    fa_tc_kernel<<<grid, NTHREADS, SMEM_BYTES>>>(Q, K, V, O, L);
}

// round 8
// speedup vs baseline: 1.3004x; 1.3004x over previous
#include <cuda_runtime.h>
#include <cstdint>

// Causal muP attention (scale=1/dhead), B=2 H=16 L=2048 D=64, fp32 in/out.
// FA2 + mma.sync.m16n8k8 TF32, 4 warps x 32 q-rows, double-buffered K/V.
// R8 = R5 (174us) + K-only odd-fastest STS.64 scatter (RNA tf32 on K).
//      V path bit-identical to R5 (coalesced gmem load + STS.32 scatter).
//      No online softmax (muP scale => fixed max 0), O never rescaled.

#define BM 128
#define BN 64
#define DD 64
#define NTHREADS 128

#define QF_FLOATS 8192           // [rowblk 0..7][kt][lane][4]
#define KF_FLOATS 4096           // per buffer: [kt][p][ln^kt][reg*2+odd]  (odd-fastest)
#define VF_FLOATS 4096           // per buffer: [kt][pd][ln^pd][odd*2+reg] (R5 layout)
#define SMEM_FLOATS (QF_FLOATS + 2*KF_FLOATS + 2*VF_FLOATS)
#define SMEM_BYTES (SMEM_FLOATS * 4)

__device__ __forceinline__ uint32_t f2tf(float f) {
    uint32_t r;
    asm("cvt.rna.tf32.f32 %0, %1;" : "=r"(r) : "f"(f));
    return r;
}
__device__ __forceinline__ float ex2(float x) {
    float y;
    asm("ex2.approx.f32 %0, %1;" : "=f"(y) : "f"(x));
    return y;
}
__device__ __forceinline__ void mma_tf32(float* d,
                                         uint32_t a0, uint32_t a1, uint32_t a2, uint32_t a3,
                                         uint32_t b0, uint32_t b1) {
    asm volatile(
        "mma.sync.aligned.m16n8k8.row.col.f32.tf32.tf32.f32 "
        "{%0,%1,%2,%3}, {%4,%5,%6,%7}, {%8,%9}, {%0,%1,%2,%3};"
        : "+f"(d[0]), "+f"(d[1]), "+f"(d[2]), "+f"(d[3])
        : "r"(a0), "r"(a1), "r"(a2), "r"(a3), "r"(b0), "r"(b1));
}

// K tile scatter: rows (n, n+8) pair into one STS.64 (odd-fastest word layout).
// kr[t] = K[(tid>>4) + t*8][d4..d4+3]; t even/odd = pair halves, p = t>>1.
__device__ __forceinline__ void scatter_k(float* Kc, const float4* kr, int tid) {
    const int d4   = (tid & 15) * 4;
    const int kt   = d4 >> 3;
    const int reg  = (d4 >> 2) & 1;
    const int r    = tid >> 4;                       // 0..7
    const int slot = (r < 4) ? (2 * r) : (2 * r - 7);
    #pragma unroll
    for (int i = 0; i < 4; i++) {                    // p = i
        const float a[4] = {kr[2*i].x,   kr[2*i].y,   kr[2*i].z,   kr[2*i].w};
        const float b[4] = {kr[2*i+1].x, kr[2*i+1].y, kr[2*i+1].z, kr[2*i+1].w};
        #pragma unroll
        for (int e = 0; e < 4; e++) {
            int ln  = (slot * 4 + e) ^ kt;           // swizzle
            int idx = ((kt * 4 + i) * 32 + ln) * 4 + reg * 2;
            *(float2*)(Kc + idx) = make_float2(
                __uint_as_float(f2tf(a[e])), __uint_as_float(f2tf(b[e])));
        }
    }
}
// V tile scatter: R5 layout, STS.32, raw fp32 (tf32 truncation in mma).
// vr[t] = V[(tid>>4) + t*8][d4..d4+3]  (coalesced gmem load)
__device__ __forceinline__ void scatter_v(float* Vc, const float4* vr, int tid) {
    const int d4  = (tid & 15) * 4;
    const int dt  = d4 >> 3;
    const int pd  = dt >> 1;
    const int odd = dt & 1;
    #pragma unroll
    for (int t = 0; t < 8; t++) {
        const int n    = (tid >> 4) + t * 8;
        const int kt   = n >> 3;
        const int regv = (n >> 2) & 1;
        const int ll   = n & 3;
        const float v[4] = {vr[t].x, vr[t].y, vr[t].z, vr[t].w};
        #pragma unroll
        for (int e = 0; e < 4; e++) {
            int ln  = (((d4 & 7) + e) * 4 + ll) ^ pd;    // swizzle
            int idx = ((kt * 4 + pd) * 32 + ln) * 4 + odd * 2 + regv;
            Vc[idx] = v[e];
        }
    }
}

__global__ __launch_bounds__(NTHREADS, 2)
void fa_tc_kernel(const float* __restrict__ Q, const float* __restrict__ K,
                  const float* __restrict__ V, float* __restrict__ O, int L)
{
    extern __shared__ float sm[];
    float* Qf  = sm;
    float* Kf0 = Qf  + QF_FLOATS;
    float* Kf1 = Kf0 + KF_FLOATS;
    float* Vf0 = Kf1 + KF_FLOATS;
    float* Vf1 = Vf0 + VF_FLOATS;
    float* Kbuf[2] = {Kf0, Kf1};
    float* Vbuf[2] = {Vf0, Vf1};

    const int qi    = (gridDim.x - 1) - blockIdx.x;   // heavy tiles first
    const int bh    = blockIdx.y;
    const int qbase = qi * BM;
    const float qscale = 1.4426950408889634f / 64.0f; // log2(e)/dhead

    const int tid  = threadIdx.x;
    const int w    = tid >> 5;      // warp 0..3, owns rows [w*32, w*32+32)
    const int lane = tid & 31;

    const float* Qg = Q + (size_t)bh * L * DD;
    const float* Kg = K + (size_t)bh * L * DD;
    const float* Vg = V + (size_t)bh * L * DD;
    float*       Og = O + (size_t)bh * L * DD;

    // ---- Q tile -> A-fragment layout (scale + RNA tf32 baked in) ----
    #pragma unroll
    for (int t = 0; t < 16; t++) {
        int fidx = tid + t * NTHREADS;      // 0..2047
        int row  = fidx >> 4;
        int d4   = (fidx & 15) * 4;
        float4 q4 = *(const float4*)(Qg + (size_t)(qbase + row) * DD + d4);
        float qv[4] = {q4.x, q4.y, q4.z, q4.w};
        int ww = row >> 4, rl = row & 15;
        #pragma unroll
        for (int e = 0; e < 4; e++) {
            int d   = d4 + e;
            int kt  = d >> 3;
            int ln  = (rl & 7) * 4 + (d & 3);
            int reg = ((rl >> 3) & 1) + (((d & 7) >= 4) ? 2 : 0);
            Qf[((ww * 8 + kt) * 32 + ln) * 4 + reg] =
                __uint_as_float(f2tf(qv[e] * qscale));
        }
    }

    // ---- prologue: tile 0 into buffer 0 ----
    {
        float4 kr[8], vr[8];
        #pragma unroll
        for (int t = 0; t < 8; t++) {
            int n = (tid >> 4) + t * 8;
            kr[t] = *(const float4*)(Kg + (size_t)n * DD + (tid & 15) * 4);
            vr[t] = *(const float4*)(Vg + (size_t)n * DD + (tid & 15) * 4);
        }
        scatter_k(Kf0, kr, tid);
        scatter_v(Vf0, vr, tid);
    }
    __syncthreads();

    // two 16-row halves per warp: h=0 rows w*32+0..15, h=1 rows w*32+16..31
    float s[2][8][4], o[2][8][4];
    float l_[2][2];
    #pragma unroll
    for (int h = 0; h < 2; h++) {
        l_[h][0] = 0.0f; l_[h][1] = 0.0f;
        #pragma unroll
        for (int dt = 0; dt < 8; dt++)
            #pragma unroll
            for (int j = 0; j < 4; j++) o[h][dt][j] = 0.0f;
    }

    const int wrow0 = qbase + w * 32;
    const int njt   = 2 * qi + 2;

    for (int jt = 0; jt < njt; jt++) {
        const int   cur       = jt & 1;
        const bool  have_next = (jt + 1 < njt);
        const int   kbase     = jt * BN;
        const bool  active    = (kbase <= wrow0 + 31);
        const float* Kc = Kbuf[cur];
        const float* Vc = Vbuf[cur];

        // prefetch next K tile to regs (gmem latency hidden by GEMM1)
        float4 kr[8];
        if (have_next) {
            const float* Kn = Kg + (size_t)(kbase + BN) * DD;
            #pragma unroll
            for (int t = 0; t < 8; t++)
                kr[t] = *(const float4*)(Kn + ((tid >> 4) + t * 8) * DD + (tid & 15) * 4);
        }

        // ---- GEMM1: S = Q K^T (B loads shared by both row halves) ----
        if (active) {
            #pragma unroll
            for (int h = 0; h < 2; h++)
                #pragma unroll
                for (int nt = 0; nt < 8; nt++)
                    #pragma unroll
                    for (int j = 0; j < 4; j++) s[h][nt][j] = 0.0f;
            #pragma unroll
            for (int kt = 0; kt < 8; kt++) {
                uint4 A0 = *(const uint4*)&Qf[(((2 * w)     * 8 + kt) * 32 + lane) * 4];
                uint4 A1 = *(const uint4*)&Qf[(((2 * w + 1) * 8 + kt) * 32 + lane) * 4];
                #pragma unroll
                for (int p = 0; p < 4; p++) {
                    // odd-fastest K word: (b.x,b.z) = nt even, (b.y,b.w) = nt odd
                    uint4 b = *(const uint4*)&Kc[((kt * 4 + p) * 32 + (lane ^ kt)) * 4];
                    mma_tf32(s[0][2 * p],     A0.x, A0.y, A0.z, A0.w, b.x, b.z);
                    mma_tf32(s[0][2 * p + 1], A0.x, A0.y, A0.z, A0.w, b.y, b.w);
                    mma_tf32(s[1][2 * p],     A1.x, A1.y, A1.z, A1.w, b.x, b.z);
                    mma_tf32(s[1][2 * p + 1], A1.x, A1.y, A1.z, A1.w, b.y, b.w);
                }
            }
        }

        // store next K tile; prefetch next V tile (R5 coalesced pattern)
        float4 vr[8];
        if (have_next) {
            scatter_k(Kbuf[cur ^ 1], kr, tid);
            const float* Vn = Vg + (size_t)(kbase + BN) * DD;
            #pragma unroll
            for (int t = 0; t < 8; t++)
                vr[t] = *(const float4*)(Vn + ((tid >> 4) + t * 8) * DD + (tid & 15) * 4);
        }

        if (active) {
            // ---- causal mask (perm-aware: c0<->kv c, c1<->kv c+4) ----
            if (kbase + BN - 1 > wrow0) {
                #pragma unroll
                for (int h = 0; h < 2; h++) {
                    int rA = wrow0 + h * 16 + (lane >> 2);
                    int rB = rA + 8;
                    #pragma unroll
                    for (int nt = 0; nt < 8; nt++) {
                        int col = kbase + nt * 8 + (lane & 3);
                        if (col     > rA) s[h][nt][0] = -1e30f;
                        if (col + 4 > rA) s[h][nt][1] = -1e30f;
                        if (col     > rB) s[h][nt][2] = -1e30f;
                        if (col + 4 > rB) s[h][nt][3] = -1e30f;
                    }
                }
            }
            // ---- softmax numerator, fixed max=0 (muP: |s| << 1) ----
            #pragma unroll
            for (int h = 0; h < 2; h++) {
                float sumA = 0.0f, sumB = 0.0f;
                #pragma unroll
                for (int nt = 0; nt < 8; nt++) {
                    float p0 = ex2(s[h][nt][0]);
                    float p1 = ex2(s[h][nt][1]);
                    float p2 = ex2(s[h][nt][2]);
                    float p3 = ex2(s[h][nt][3]);
                    sumA += p0 + p1;
                    sumB += p2 + p3;
                    s[h][nt][0] = p0;
                    s[h][nt][1] = p1;
                    s[h][nt][2] = p2;
                    s[h][nt][3] = p3;
                }
                l_[h][0] += sumA;
                l_[h][1] += sumB;
            }
            // ---- GEMM2: O += P V (P = s regs, order {0,2,1,3}; shared B) ----
            #pragma unroll
            for (int kt = 0; kt < 8; kt++) {
                uint32_t p00 = __float_as_uint(s[0][kt][0]);
                uint32_t p01 = __float_as_uint(s[0][kt][2]);
                uint32_t p02 = __float_as_uint(s[0][kt][1]);
                uint32_t p03 = __float_as_uint(s[0][kt][3]);
                uint32_t p10 = __float_as_uint(s[1][kt][0]);
                uint32_t p11 = __float_as_uint(s[1][kt][2]);
                uint32_t p12 = __float_as_uint(s[1][kt][1]);
                uint32_t p13 = __float_as_uint(s[1][kt][3]);
                #pragma unroll
                for (int pd = 0; pd < 4; pd++) {
                    // R5 V word: (b.x,b.y) = dt even, (b.z,b.w) = dt odd
                    uint4 b = *(const uint4*)&Vc[((kt * 4 + pd) * 32 + (lane ^ pd)) * 4];
                    mma_tf32(o[0][2 * pd],     p00, p01, p02, p03, b.x, b.y);
                    mma_tf32(o[0][2 * pd + 1], p00, p01, p02, p03, b.z, b.w);
                    mma_tf32(o[1][2 * pd],     p10, p11, p12, p13, b.x, b.y);
                    mma_tf32(o[1][2 * pd + 1], p10, p11, p12, p13, b.z, b.w);
                }
            }
        }

        if (have_next) {
            scatter_v(Vbuf[cur ^ 1], vr, tid);
            __syncthreads();
        }
    }

    // ---- epilogue: reduce l across quad, normalize, store ----
    #pragma unroll
    for (int h = 0; h < 2; h++) {
        float lA = l_[h][0], lB = l_[h][1];
        lA += __shfl_xor_sync(0xffffffffu, lA, 1);
        lA += __shfl_xor_sync(0xffffffffu, lA, 2);
        lB += __shfl_xor_sync(0xffffffffu, lB, 1);
        lB += __shfl_xor_sync(0xffffffffu, lB, 2);
        float invA = 1.0f / lA;
        float invB = 1.0f / lB;

        int rA = qbase + w * 32 + h * 16 + (lane >> 2);
        int rB = rA + 8;
        #pragma unroll
        for (int dt = 0; dt < 8; dt++) {
            int d0 = dt * 8 + 2 * (lane & 3);
            float2 oa = make_float2(o[h][dt][0] * invA, o[h][dt][1] * invA);
            float2 ob = make_float2(o[h][dt][2] * invB, o[h][dt][3] * invB);
            *(float2*)(Og + (size_t)rA * DD + d0) = oa;
            *(float2*)(Og + (size_t)rB * DD + d0) = ob;
        }
    }
}

extern "C" void kernel_launch(void* const* d_in, const int* in_sizes, int n_in,
                              void* d_out, int out_size)
{
    const float* Q = (const float*)d_in[0];
    const float* K = (const float*)d_in[1];
    const float* V = (const float*)d_in[2];
    float* O = (float*)d_out;

    const int L  = 2048;
    const int BH = 2 * 16;

    cudaFuncSetAttribute(fa_tc_kernel,
                         cudaFuncAttributeMaxDynamicSharedMemorySize, SMEM_BYTES);

    dim3 grid(L / BM, BH);    // (16, 32)
    fa_tc_kernel<<<grid, NTHREADS, SMEM_BYTES>>>(Q, K, V, O, L);
}